// round 6
// baseline (speedup 1.0000x reference)
#include <cuda_runtime.h>
#include <stdint.h>
#include <math.h>

// Problem constants (fixed shapes: scores (128, 4096, 2))
#define NN   4096
#define BSZ  128
#define ENS  2
#define BE   256           // BSZ*ENS
#define KK   32
#define NEGC (-1e30f)
#define HALF_OUT 1048576   // 128*4096*2
#define NCHUNK 32
#define CLEN   128         // NN / NCHUNK
#define NBAND  8
#define BLEN   512         // NN / NBAND

// persistent-kernel sizing: 148 SMs x 7 blocks (launch_bounds allows 8 -> slack)
#define BK_BLK  64                      // backward blocks (4 warps each -> 256 b)
#define W_BLK   972                     // worker blocks
#define W_WARP  (W_BLK * 4)             // 3888 worker warps
#define GRID    (BK_BLK + W_BLK)        // 1036

// ---------------- scratch (static device memory) ----------------
__device__ float    g_B[(size_t)(NN + 1) * BE * KK]; // B[i][b][j-1]
__device__ float    g_F[(size_t)NN * BE * KK];       // F[i][b][j] + th_i - off_b
__device__ unsigned g_mask[(size_t)BE * NN];         // inclusion masks [b*NN + i]
__device__ float    g_CE[(size_t)BE * NCHUNK * KK];  // chunk ESPs
__device__ float    g_BD[(size_t)BE * NCHUNK * KK];  // chunk boundary prefixes
__device__ float    g_M[(size_t)NN * BE];            // unnormalized marginals [i*BE + b]
__device__ float    g_off[BE];                       // fast log e_31 (early normalizer)
__device__ float    g_scale[BE];                     // exp(off - logZ_exact)
__device__ unsigned g_bits[(size_t)BE * (NN / 32)];  // sampled bits

// progress counters (reset each run by k_reset)
__device__ int g_prog[NBAND];   // backward band completions (target 256 each)
__device__ int g_doneA;         // phaseA warps done (target W_WARP)
__device__ int g_doneM;         // merge warps done (target 256)
__device__ int g_doneC;         // phaseC warps done (target W_WARP)
__device__ int g_doneS;         // sampler chains + scale done (target 256)
__device__ int g_doneCb;        // comb block-items done (target 8192)

__global__ void k_reset()
{
    if (threadIdx.x < NBAND) g_prog[threadIdx.x] = 0;
    if (threadIdx.x == 0) { g_doneA = 0; g_doneM = 0; g_doneC = 0; g_doneS = 0; g_doneCb = 0; }
}

// ---------------- threefry2x32, key = (0, 42) ----------------
__device__ __forceinline__ uint32_t tf_bits(uint32_t lo)
{
    uint32_t x0 = 0u;
    uint32_t x1 = lo;
    const uint32_t ks0 = 0u, ks1 = 42u, ks2 = 0x1BD11BF0u;
    x0 += ks0; x1 += ks1;
#define TFR(r) { x0 += x1; x1 = (x1 << (r)) | (x1 >> (32 - (r))); x1 ^= x0; }
    TFR(13) TFR(15) TFR(26) TFR(6)   x0 += ks1; x1 += ks2 + 1u;
    TFR(17) TFR(29) TFR(16) TFR(24)  x0 += ks2; x1 += ks0 + 2u;
    TFR(13) TFR(15) TFR(26) TFR(6)   x0 += ks0; x1 += ks1 + 3u;
    TFR(17) TFR(29) TFR(16) TFR(24)  x0 += ks1; x1 += ks2 + 4u;
    TFR(13) TFR(15) TFR(26) TFR(6)   x0 += ks2; x1 += ks0 + 5u;
#undef TFR
    return x0 ^ x1;
}

// EXACT logaddexp (libdevice — bitwise path for sampling masks)
__device__ __forceinline__ float logaddexpf32(float x, float y)
{
    float d = x - y;
    return fmaxf(x, y) + log1pf(expf(-fabsf(d)));
}

// Fast logaddexp (marginals path, 1e-3 tolerance)
__device__ __forceinline__ float logaddexp_fast(float x, float y)
{
    float d = x - y;
    return fmaxf(x, y) + __logf(1.0f + __expf(-fabsf(d)));
}

__device__ __forceinline__ void waitge(int* p, int target)
{
    volatile int* vp = (volatile int*)p;
    while (*vp < target) __nanosleep(256);
}

// ---------------- sampler helpers (numerics unchanged) ----------------
__device__ __forceinline__ void samp_word(unsigned m, int ii, unsigned& r, unsigned& w)
{
    unsigned incl = (unsigned)(r > 0) & ((m >> ((r - 1u) & 31u)) & 1u);
    r -= incl;
    w |= incl << ii;
}

__device__ __forceinline__ unsigned samp_block(const uint4* buf, unsigned& r)
{
    unsigned w = 0;
#pragma unroll
    for (int q = 0; q < 8; ++q) {
        uint4 v = buf[q];
        samp_word(v.x, 4 * q + 0, r, w);
        samp_word(v.y, 4 * q + 1, r, w);
        samp_word(v.z, 4 * q + 2, r, w);
        samp_word(v.w, 4 * q + 3, r, w);
    }
    return w;
}

// ---------------- backward (exact) + scale + per-b sampler ----------------
__device__ void backward_role(const float* __restrict__ scores)
{
    int lane = threadIdx.x & 31;
    int b = blockIdx.x * 4 + (threadIdx.x >> 5);
    const int bz = b >> 1, e = b & 1;
    const float* thbase = scores + (size_t)bz * (NN * ENS) + e;

    float E = NEGC;
    g_B[((size_t)NN * BE + b) * KK + lane] = NEGC;   // init row (i = NN)

    for (int s = 0; s < NBAND; ++s) {
        int blk_hi = 128 - 16 * s;         // exclusive
        int blk_lo = blk_hi - 16;
        for (int blk = blk_hi - 1; blk >= blk_lo; --blk) {
            int base = blk * 32;
            float thv = thbase[2 * (base + lane)];
            // inline threefry uniform (bit-identical to jax.random.uniform index i*BE+b)
            uint32_t rb = tf_bits((uint32_t)((base + lane) * BE + b));
            float uv = fmaxf(__uint_as_float((rb >> 9) | 0x3f800000u) - 1.0f, 0.0f);
#pragma unroll 8
            for (int ii = 31; ii >= 0; --ii) {
                int i = base + ii;
                float th = __shfl_sync(0xffffffffu, thv, ii);
                float u  = __shfl_sync(0xffffffffu, uv,  ii);
                float Ep = __shfl_up_sync(0xffffffffu, E, 1);
                if (lane == 0) Ep = 0.0f;
                float shifted = Ep + th;
                float Enew = logaddexpf32(E, shifted);
                float logq = shifted - Enew;
                float q = expf(fminf(logq, 0.0f));
                unsigned m = __ballot_sync(0xffffffffu, u < q);
                E = Enew;
                g_B[((size_t)i * BE + b) * KK + lane] = E;
                if (lane == 0) g_mask[(size_t)b * NN + i] = m;
            }
        }
        __threadfence();
        __syncwarp();
        if (lane == 0) atomicAdd(&g_prog[s], 1);
    }

    // exact logZ = B[0][b][32] = final E on lane 31
    float lz = __shfl_sync(0xffffffffu, E, 31);

    if (lane == 0) {
        // normalizer scale = exp(off - logZ); merge is long done by now
        waitge(&g_doneM, BE);
        __threadfence();
        g_scale[b] = __expf(g_off[b] - lz);

        // sampler: consumes masks this warp wrote itself (no gate needed)
        const uint4* mp = reinterpret_cast<const uint4*>(g_mask + (size_t)b * NN);
        unsigned r = KK;
        uint4 A[8], Bb[8];
#pragma unroll
        for (int q = 0; q < 8; ++q) A[q] = mp[q];
        for (int blk = 0; blk < 128; blk += 2) {
#pragma unroll
            for (int q = 0; q < 8; ++q) Bb[q] = mp[(blk + 1) * 8 + q];
            g_bits[(size_t)b * 128 + blk] = samp_block(A, r);
            if (blk + 2 < 128) {
#pragma unroll
                for (int q = 0; q < 8; ++q) A[q] = mp[(blk + 2) * 8 + q];
            }
            g_bits[(size_t)b * 128 + blk + 1] = samp_block(Bb, r);
        }
        __threadfence();
        atomicAdd(&g_doneS, 1);
    }
}

// ---------------- worker pieces ----------------
__device__ void phaseA_item(const float* __restrict__ scores, int q)
{
    int lane = threadIdx.x & 31;
    int b = q >> 5;
    int c = q & 31;
    const int bz = b >> 1, e = b & 1;
    const float* thbase = scores + (size_t)bz * (NN * ENS) + e;

    float F = (lane == 0) ? 0.0f : NEGC;
    int base0 = c * CLEN;
    for (int blk = 0; blk < CLEN / 32; ++blk) {
        float thv = thbase[2 * (base0 + blk * 32 + lane)];
#pragma unroll 8
        for (int ii = 0; ii < 32; ++ii) {
            float th = __shfl_sync(0xffffffffu, thv, ii);
            float Fp = __shfl_up_sync(0xffffffffu, F, 1);
            if (lane == 0) Fp = NEGC;
            F = logaddexp_fast(F, Fp + th);
        }
    }
    g_CE[((size_t)b * NCHUNK + c) * KK + lane] = F;
}

__device__ void merge_item(int b)
{
    int lane = threadIdx.x & 31;
    float P = (lane == 0) ? 0.0f : NEGC;
    for (int c = 0; c < NCHUNK; ++c) {
        g_BD[((size_t)b * NCHUNK + c) * KK + lane] = P;
        float L = g_CE[((size_t)b * NCHUNK + c) * KK + lane];
        float mx = NEGC;
#pragma unroll
        for (int m = 0; m < 32; ++m) {
            float Pm = __shfl_sync(0xffffffffu, P, m);
            float Lx = __shfl_sync(0xffffffffu, L, (lane - m) & 31);
            if (m <= lane) mx = fmaxf(mx, Pm + Lx);
        }
        float sum = 0.0f;
#pragma unroll
        for (int m = 0; m < 32; ++m) {
            float Pm = __shfl_sync(0xffffffffu, P, m);
            float Lx = __shfl_sync(0xffffffffu, L, (lane - m) & 31);
            if (m <= lane) sum += __expf(Pm + Lx - mx);
        }
        P = mx + __logf(sum);
    }
    // NOTE: P[31] = log e_31 (NOT logZ = log e_32) — used only as an early
    // normalization offset; the exact logZ correction happens via g_scale.
    if (lane == 31) g_off[b] = P;
}

__device__ void phaseC_item(const float* __restrict__ scores, int q)
{
    int lane = threadIdx.x & 31;
    int b = q >> 5;
    int c = q & 31;
    const int bz = b >> 1, e = b & 1;
    const float* thbase = scores + (size_t)bz * (NN * ENS) + e;

    float F = g_BD[((size_t)b * NCHUNK + c) * KK + lane];
    float off = g_off[b];
    int base0 = c * CLEN;
    for (int blk = 0; blk < CLEN / 32; ++blk) {
        float thv = thbase[2 * (base0 + blk * 32 + lane)];
#pragma unroll 8
        for (int ii = 0; ii < 32; ++ii) {
            int i = base0 + blk * 32 + ii;
            float th = __shfl_sync(0xffffffffu, thv, ii);
            g_F[((size_t)i * BE + b) * KK + lane] = F + (th - off);  // bake th - off
            float Fp = __shfl_up_sync(0xffffffffu, F, 1);
            if (lane == 0) Fp = NEGC;
            F = logaddexp_fast(F, Fp + th);
        }
    }
}

__device__ void comb_item(int t)
{
    int s = t >> 10, u = t & 1023;
    int bandlo = 3584 - 512 * s;
    int p = u * 128 + threadIdx.x;
    int b = p & 255;
    int i = bandlo + (p >> 8);

    const float4* Fr = reinterpret_cast<const float4*>(&g_F[((size_t)i * BE + b) * KK]);
    const float4* Br = reinterpret_cast<const float4*>(&g_B[((size_t)(i + 1) * BE + b) * KK]);

    float Bv[32];
#pragma unroll
    for (int q = 0; q < 8; ++q) {
        float4 v = Br[q];
        Bv[4 * q + 0] = v.x; Bv[4 * q + 1] = v.y; Bv[4 * q + 2] = v.z; Bv[4 * q + 3] = v.w;
    }
    float m = 0.0f;
#pragma unroll
    for (int q = 0; q < 8; ++q) {
        float4 f = Fr[q];
        float fj[4] = { f.x, f.y, f.z, f.w };
#pragma unroll
        for (int r = 0; r < 4; ++r) {
            int j = 4 * q + r;
            float bc = (j == 31) ? 0.0f : Bv[30 - j];  // B[i+1][31-j]; col 0 == 0
            m += __expf(fj[r] + bc);
        }
    }
    g_M[(size_t)i * BE + b] = m;   // unnormalized: true_m * exp(logZ - off)... scaled later
}

__device__ void final_item(int t, float* __restrict__ out)
{
    int g = t * 128 + threadIdx.x;        // 0 .. 2^20-1
    int bz = g >> 13;
    int rem = g & 8191;
    int n = rem >> 1;
    int e = rem & 1;
    int be = bz * 2 + e;
    float s = (float)((g_bits[(size_t)be * 128 + (n >> 5)] >> (n & 31)) & 1u);
    float m = g_M[(size_t)n * BE + be] * g_scale[be];
    out[g] = (s - m) + m;
    out[HALF_OUT + g] = m;
}

// ---------------- the persistent kernel ----------------
__global__ void __launch_bounds__(128, 8)
k_all(const float* __restrict__ scores, float* __restrict__ out)
{
    if (blockIdx.x < BK_BLK) {
        backward_role(scores);
        return;
    }

    int wb   = blockIdx.x - BK_BLK;            // 0..W_BLK-1
    int lane = threadIdx.x & 31;
    int wW   = wb * 4 + (threadIdx.x >> 5);    // worker warp id

    // phase A
    for (int q = wW; q < BE * NCHUNK; q += W_WARP) phaseA_item(scores, q);
    __threadfence();
    __syncwarp();
    if (lane == 0) atomicAdd(&g_doneA, 1);

    // merge (warps 0..255)
    if (wW < BE) {
        if (lane == 0) waitge(&g_doneA, W_WARP);
        __syncwarp();
        __threadfence();
        merge_item(wW);
        __threadfence();
        __syncwarp();
        if (lane == 0) atomicAdd(&g_doneM, 1);
    }

    // phase C
    if (lane == 0) waitge(&g_doneM, BE);
    __syncwarp();
    __threadfence();
    for (int q = wW; q < BE * NCHUNK; q += W_WARP) phaseC_item(scores, q);
    __threadfence();
    __syncwarp();
    if (lane == 0) atomicAdd(&g_doneC, 1);

    // comb (block-granular items, bands chase the backward scan)
    {
        bool haveC = false;
        int gated_s = -1;
        for (int t = wb; t < 8192; t += W_BLK) {
            int s = t >> 10;
            if (threadIdx.x == 0) {
                if (!haveC) { waitge(&g_doneC, W_WARP); haveC = true; }
                if (s > gated_s) { waitge(&g_prog[s], BE); gated_s = s; }
            }
            __syncthreads();
            __threadfence();
            comb_item(t);
            __threadfence();
            __syncthreads();
            if (threadIdx.x == 0) atomicAdd(&g_doneCb, 1);
        }
    }

    // final repack (gated on all comb + all sampler chains & scales)
    if (threadIdx.x == 0) {
        waitge(&g_doneCb, 8192);
        waitge(&g_doneS, BE);
    }
    __syncthreads();
    __threadfence();
    for (int t = wb; t < 8192; t += W_BLK) final_item(t, out);
}

extern "C" void kernel_launch(void* const* d_in, const int* in_sizes, int n_in,
                              void* d_out, int out_size)
{
    const float* scores = (const float*)d_in[0];
    float* out = (float*)d_out;
    (void)in_sizes; (void)n_in; (void)out_size;

    k_reset<<<1, 32>>>();
    k_all<<<GRID, 128>>>(scores, out);
}

// round 7
// speedup vs baseline: 1.3936x; 1.3936x over previous
#include <cuda_runtime.h>
#include <stdint.h>
#include <math.h>

// Problem constants (fixed shapes: scores (128, 4096, 2))
#define NN   4096
#define BSZ  128
#define ENS  2
#define BE   256           // BSZ*ENS
#define KK   32
#define NEGC (-1e30f)
#define HALF_OUT 1048576   // 128*4096*2
#define NCHUNK 32
#define CLEN   128         // NN / NCHUNK
#define NSLICE 8
#define SLEN   512         // NN / NSLICE

// ---------------- scratch (static device memory) ----------------
__device__ float    g_B[(size_t)(NN + 1) * BE * KK]; // B[i][b][j-1]
__device__ float    g_F[(size_t)NN * BE * KK];       // F[i][b][j] (pre-update)
__device__ unsigned g_mask[(size_t)BE * NN];         // inclusion masks [b*NN + i]
__device__ float    g_CE[(size_t)BE * NCHUNK * KK];  // chunk ESPs
__device__ float    g_BD[(size_t)BE * NCHUNK * KK];  // chunk boundary prefixes
__device__ float    g_S[(size_t)NN * BE];            // th + log_ekm1 (unnormalized)
__device__ float    g_T[(size_t)NN * BE];            // transposed theta [i*BE + b]
__device__ float    g_E[(size_t)BE * KK];            // backward state between slices
__device__ float    g_logZ[BE];
__device__ unsigned g_bits[(size_t)BE * (NN / 32)];  // sampled bits

// ---------------- threefry2x32, key = (0, 42) ----------------
__device__ __forceinline__ uint32_t tf_bits(uint32_t lo)
{
    uint32_t x0 = 0u;
    uint32_t x1 = lo;
    const uint32_t ks0 = 0u, ks1 = 42u, ks2 = 0x1BD11BF0u;
    x0 += ks0; x1 += ks1;
#define TFR(r) { x0 += x1; x1 = (x1 << (r)) | (x1 >> (32 - (r))); x1 ^= x0; }
    TFR(13) TFR(15) TFR(26) TFR(6)   x0 += ks1; x1 += ks2 + 1u;
    TFR(17) TFR(29) TFR(16) TFR(24)  x0 += ks2; x1 += ks0 + 2u;
    TFR(13) TFR(15) TFR(26) TFR(6)   x0 += ks0; x1 += ks1 + 3u;
    TFR(17) TFR(29) TFR(16) TFR(24)  x0 += ks1; x1 += ks2 + 4u;
    TFR(13) TFR(15) TFR(26) TFR(6)   x0 += ks2; x1 += ks0 + 5u;
#undef TFR
    return x0 ^ x1;
}

// EXACT logaddexp (libdevice — bitwise path for sampling masks)
__device__ __forceinline__ float logaddexpf32(float x, float y)
{
    float d = x - y;
    return fmaxf(x, y) + log1pf(expf(-fabsf(d)));
}

// Fast logaddexp (marginals path, 1e-3 tolerance)
__device__ __forceinline__ float logaddexp_fast(float x, float y)
{
    float d = x - y;
    return fmaxf(x, y) + __logf(1.0f + __expf(-fabsf(d)));
}

// ---------------- sampler helpers (numerics unchanged) ----------------
__device__ __forceinline__ void samp_word(unsigned m, int ii, unsigned& r, unsigned& w)
{
    unsigned incl = (unsigned)(r > 0) & ((m >> ((r - 1u) & 31u)) & 1u);
    r -= incl;
    w |= incl << ii;
}

__device__ __forceinline__ unsigned samp_block(const uint4* buf, unsigned& r)
{
    unsigned w = 0;
#pragma unroll
    for (int q = 0; q < 8; ++q) {
        uint4 v = buf[q];
        samp_word(v.x, 4 * q + 0, r, w);
        samp_word(v.y, 4 * q + 1, r, w);
        samp_word(v.z, 4 * q + 2, r, w);
        samp_word(v.w, 4 * q + 3, r, w);
    }
    return w;
}

// ---------------- backward slice (exact chain, DEFERRED ballots) ----------------
__device__ void backward_slice(const float* __restrict__ scores, int s)
{
    int lane = threadIdx.x & 31;
    int b = blockIdx.x * 4 + (threadIdx.x >> 5);
    const int bz = b >> 1, e = b & 1;
    const float* thbase = scores + (size_t)bz * (NN * ENS) + e;

    float E;
    if (s == 0) {
        E = NEGC;
        g_B[((size_t)NN * BE + b) * KK + lane] = NEGC;   // init row (i = NN)
    } else {
        E = g_E[(size_t)b * KK + lane];
    }

    int blk_hi = (NN / 32) - 16 * s;        // exclusive
    int blk_lo = blk_hi - 16;

    // prefetch theta for the first block of this slice
    float thv = thbase[2 * ((blk_hi - 1) * 32 + lane)];

    for (int blk = blk_hi - 1; blk >= blk_lo; --blk) {
        int base = blk * 32;
        float thv_next = (blk > blk_lo) ? thbase[2 * ((blk - 1) * 32 + lane)] : 0.0f;
        // inline threefry uniform (bit-identical to jax.random.uniform, index i*BE+b)
        uint32_t rb = tf_bits((uint32_t)((base + lane) * BE + b));
        float uv = fmaxf(__uint_as_float((rb >> 9) | 0x3f800000u) - 1.0f, 0.0f);

#pragma unroll
        for (int g8 = 3; g8 >= 0; --g8) {
            float lq[8];
            // chain segment: 8 exact steps; ballots deferred (off critical path)
#pragma unroll
            for (int t = 7; t >= 0; --t) {
                int ii = g8 * 8 + t;
                float th = __shfl_sync(0xffffffffu, thv, ii);
                float Ep = __shfl_up_sync(0xffffffffu, E, 1);
                if (lane == 0) Ep = 0.0f;
                float shifted = Ep + th;
                float Enew = logaddexpf32(E, shifted);
                lq[t] = shifted - Enew;       // logq, buffered
                E = Enew;
                g_B[((size_t)(base + ii) * BE + b) * KK + lane] = E;
            }
            // deferred mask generation: 8 independent expf+ballot, pipelined
#pragma unroll
            for (int t = 7; t >= 0; --t) {
                int ii = g8 * 8 + t;
                float u = __shfl_sync(0xffffffffu, uv, ii);
                float q = expf(fminf(lq[t], 0.0f));
                unsigned m = __ballot_sync(0xffffffffu, u < q);
                if (lane == 0) g_mask[(size_t)b * NN + base + ii] = m;
            }
        }
        thv = thv_next;
    }

    if (s < NSLICE - 1) {
        g_E[(size_t)b * KK + lane] = E;
        return;
    }

    // ---- slice 7: exact logZ + per-b sampler (consumes this warp's own masks) ----
    float lz = __shfl_sync(0xffffffffu, E, 31);   // B[0][b][32] = logZ
    if (lane == 0) {
        g_logZ[b] = lz;
        const uint4* mp = reinterpret_cast<const uint4*>(g_mask + (size_t)b * NN);
        unsigned r = KK;
        uint4 A[8], Bb[8];
#pragma unroll
        for (int q = 0; q < 8; ++q) A[q] = mp[q];
        for (int blk = 0; blk < 128; blk += 2) {
#pragma unroll
            for (int q = 0; q < 8; ++q) Bb[q] = mp[(blk + 1) * 8 + q];
            g_bits[(size_t)b * 128 + blk] = samp_block(A, r);
            if (blk + 2 < 128) {
#pragma unroll
                for (int q = 0; q < 8; ++q) A[q] = mp[(blk + 2) * 8 + q];
            }
            g_bits[(size_t)b * 128 + blk + 1] = samp_block(Bb, r);
        }
    }
}

// ---------------- worker pieces (unchanged from R4 numerics) ----------------
__device__ void phaseA(const float* __restrict__ scores, int xb)
{
    int lane = threadIdx.x & 31;
    int wid = xb * 4 + (threadIdx.x >> 5);   // 0..8191
    int b = wid >> 5;
    int c = wid & 31;
    const int bz = b >> 1, e = b & 1;
    const float* thbase = scores + (size_t)bz * (NN * ENS) + e;

    float F = (lane == 0) ? 0.0f : NEGC;
    int base0 = c * CLEN;
    for (int blk = 0; blk < CLEN / 32; ++blk) {
        float thv = thbase[2 * (base0 + blk * 32 + lane)];
#pragma unroll 8
        for (int ii = 0; ii < 32; ++ii) {
            float th = __shfl_sync(0xffffffffu, thv, ii);
            float Fp = __shfl_up_sync(0xffffffffu, F, 1);
            if (lane == 0) Fp = NEGC;
            F = logaddexp_fast(F, Fp + th);
        }
    }
    g_CE[((size_t)b * NCHUNK + c) * KK + lane] = F;
}

__device__ void transpose_theta(const float* __restrict__ scores, int xb)
{
    int idx = (xb * 128 + threadIdx.x) * 4;
#pragma unroll
    for (int q = 0; q < 4; ++q, ++idx) {
        int b = idx & (BE - 1);
        int i = idx >> 8;
        g_T[idx] = scores[(size_t)(b >> 1) * (NN * ENS) + i * ENS + (b & 1)];
    }
}

__device__ void merge_chunks(int xb)
{
    int lane = threadIdx.x & 31;
    int b = xb * 4 + (threadIdx.x >> 5);

    float P = (lane == 0) ? 0.0f : NEGC;
    for (int c = 0; c < NCHUNK; ++c) {
        g_BD[((size_t)b * NCHUNK + c) * KK + lane] = P;  // exclusive prefix
        float L = g_CE[((size_t)b * NCHUNK + c) * KK + lane];
        float mx = NEGC;
#pragma unroll
        for (int m = 0; m < 32; ++m) {
            float Pm = __shfl_sync(0xffffffffu, P, m);
            float Lx = __shfl_sync(0xffffffffu, L, (lane - m) & 31);
            if (m <= lane) mx = fmaxf(mx, Pm + Lx);
        }
        float sum = 0.0f;
#pragma unroll
        for (int m = 0; m < 32; ++m) {
            float Pm = __shfl_sync(0xffffffffu, P, m);
            float Lx = __shfl_sync(0xffffffffu, L, (lane - m) & 31);
            if (m <= lane) sum += __expf(Pm + Lx - mx);
        }
        P = mx + __logf(sum);
    }
}

__device__ void phaseC_storeF(const float* __restrict__ scores, int xb)
{
    int lane = threadIdx.x & 31;
    int wid = xb * 4 + (threadIdx.x >> 5);
    int b = wid >> 5;
    int c = wid & 31;
    const int bz = b >> 1, e = b & 1;
    const float* thbase = scores + (size_t)bz * (NN * ENS) + e;

    float F = g_BD[((size_t)b * NCHUNK + c) * KK + lane];
    int base0 = c * CLEN;
    for (int blk = 0; blk < CLEN / 32; ++blk) {
        float thv = thbase[2 * (base0 + blk * 32 + lane)];
#pragma unroll 8
        for (int ii = 0; ii < 32; ++ii) {
            int i = base0 + blk * 32 + ii;
            g_F[((size_t)i * BE + b) * KK + lane] = F;
            float th = __shfl_sync(0xffffffffu, thv, ii);
            float Fp = __shfl_up_sync(0xffffffffu, F, 1);
            if (lane == 0) Fp = NEGC;
            F = logaddexp_fast(F, Fp + th);
        }
    }
}

__device__ void comb_band(int xb, int rowbase)
{
    int tid = xb * 128 + threadIdx.x;
    int b = tid & (BE - 1);
    int i = rowbase + (tid >> 8);

    const float4* Fr = reinterpret_cast<const float4*>(&g_F[((size_t)i * BE + b) * KK]);
    const float4* Br = reinterpret_cast<const float4*>(&g_B[((size_t)(i + 1) * BE + b) * KK]);

    float Fv[32], Bv[32];
#pragma unroll
    for (int q = 0; q < 8; ++q) {
        float4 f4 = Fr[q];
        Fv[4 * q + 0] = f4.x; Fv[4 * q + 1] = f4.y; Fv[4 * q + 2] = f4.z; Fv[4 * q + 3] = f4.w;
        float4 b4 = Br[q];
        Bv[4 * q + 0] = b4.x; Bv[4 * q + 1] = b4.y; Bv[4 * q + 2] = b4.z; Bv[4 * q + 3] = b4.w;
    }

    float comb[32];
#pragma unroll
    for (int j = 0; j < 32; ++j) {
        float bc = (j == 31) ? 0.0f : Bv[30 - j];   // B[i+1][31-j]; col 0 == 0
        comb[j] = Fv[j] + bc;
    }
    float mx = comb[0];
#pragma unroll
    for (int j = 1; j < 32; ++j) mx = fmaxf(mx, comb[j]);
    float sum = 0.0f;
#pragma unroll
    for (int j = 0; j < 32; ++j) sum += __expf(comb[j] - mx);

    g_S[(size_t)i * BE + b] = g_T[(size_t)i * BE + b] + mx + __logf(sum);
}

// ---------------- sliced fused kernel ----------------
__global__ void k_slice(const float* __restrict__ scores, int s)
{
    if (blockIdx.x < 64) {
        backward_slice(scores, s);
        return;
    }
    int xb = blockIdx.x - 64;
    if (s == 0) {
        if (xb < 2048) phaseA(scores, xb);
        else transpose_theta(scores, xb - 2048);
    } else if (s == 1) {
        merge_chunks(xb);
    } else if (s == 2) {
        phaseC_storeF(scores, xb);
    } else {
        // comb bands chase the backward scan down:
        // s=3 -> rows [2560,4096); s=4..7 -> [4096-512s, 4096-512(s-1))
        int rowbase = (s == 3) ? 2560 : (NN - SLEN * s);
        comb_band(xb, rowbase);
    }
}

// ---------------- tail: last comb band only ----------------
__global__ void k_tail()
{
    comb_band(blockIdx.x, 0);   // rows [0, 512)
}

// ---------------- finalize ----------------
__global__ void k_final(float* __restrict__ out)
{
    int tid = blockIdx.x * blockDim.x + threadIdx.x;  // 0 .. 2^20-1
    int bz = tid >> 13;
    int rem = tid & 8191;
    int n = rem >> 1;
    int e = rem & 1;
    int be = bz * ENS + e;
    float s = (float)((g_bits[(size_t)be * (NN / 32) + (n >> 5)] >> (n & 31)) & 1u);
    float m = __expf(g_S[(size_t)n * BE + be] - g_logZ[be]);
    out[tid] = (s - m) + m;
    out[HALF_OUT + tid] = m;
}

extern "C" void kernel_launch(void* const* d_in, const int* in_sizes, int n_in,
                              void* d_out, int out_size)
{
    const float* scores = (const float*)d_in[0];
    float* out = (float*)d_out;
    (void)in_sizes; (void)n_in; (void)out_size;

    k_slice<<<64 + 2048 + 2048, 128>>>(scores, 0);  // backward + phaseA + transpose
    k_slice<<<64 + 64,          128>>>(scores, 1);  // backward + merge
    k_slice<<<64 + 2048,        128>>>(scores, 2);  // backward + phaseC (store F)
    k_slice<<<64 + 3072,        128>>>(scores, 3);  // backward + comb [2560,4096)
    k_slice<<<64 + 1024,        128>>>(scores, 4);  // backward + comb [2048,2560)
    k_slice<<<64 + 1024,        128>>>(scores, 5);  // backward + comb [1536,2048)
    k_slice<<<64 + 1024,        128>>>(scores, 6);  // backward + comb [1024,1536)
    k_slice<<<64 + 1024,        128>>>(scores, 7);  // backward + comb [512,1024) + sampler
    k_tail<<<1024, 128>>>();                        // comb [0,512)
    k_final<<<2048, 512>>>(out);
}